// round 1
// baseline (speedup 1.0000x reference)
#include <cuda_runtime.h>
#include <math.h>

// Problem dims (fixed)
#define BB 8
#define LL 2048
#define EE 1024
#define HH 16
#define DD 64
#define MM (BB*LL)      // 16384 rows
#define FF (4*EE)       // 4096 ffn dim

#define LN_EPS 1e-5f
#define ATTN_EPS 1e-6f

// ---------------- scratch (device globals; no runtime allocation) ----------------
__device__ float g_h1[(size_t)MM * EE];   // LN1 out; reused as attn output
__device__ float g_q [(size_t)MM * EE];
__device__ float g_k [(size_t)MM * EE];   // reused as LN2 out (h2)
__device__ float g_v [(size_t)MM * EE];
__device__ float g_x2[(size_t)MM * EE];   // residual after attention block
__device__ float g_f1[(size_t)MM * FF];   // FFN intermediate
__device__ float g_kv[BB * HH * DD * DD]; // KV[bh][d][m]
__device__ float g_ks[BB * HH * DD];      // Ksum[bh][d]

// ---------------- LayerNorm: one block per row ----------------
__global__ void ln_kernel(const float* __restrict__ x,
                          const float* __restrict__ g,
                          const float* __restrict__ b,
                          float* __restrict__ y)
{
    const int row = blockIdx.x;
    const int tid = threadIdx.x;          // 256 threads, 4 floats each
    const float4* xr = (const float4*)(x + (size_t)row * EE);
    float4 v = xr[tid];
    float s  = v.x + v.y + v.z + v.w;
    float sq = v.x*v.x + v.y*v.y + v.z*v.z + v.w*v.w;

    #pragma unroll
    for (int off = 16; off > 0; off >>= 1) {
        s  += __shfl_xor_sync(0xffffffffu, s,  off);
        sq += __shfl_xor_sync(0xffffffffu, sq, off);
    }
    __shared__ float ws[8], wsq[8];
    __shared__ float s_mean, s_rstd;
    const int wid = tid >> 5, lane = tid & 31;
    if (lane == 0) { ws[wid] = s; wsq[wid] = sq; }
    __syncthreads();
    if (tid == 0) {
        float ts = 0.f, tsq = 0.f;
        #pragma unroll
        for (int i = 0; i < 8; i++) { ts += ws[i]; tsq += wsq[i]; }
        float mean = ts * (1.0f / EE);
        float var  = tsq * (1.0f / EE) - mean * mean;
        s_mean = mean;
        s_rstd = rsqrtf(var + LN_EPS);
    }
    __syncthreads();
    const float mean = s_mean, rstd = s_rstd;
    float4 gg = ((const float4*)g)[tid];
    float4 bb = ((const float4*)b)[tid];
    float4 o;
    o.x = (v.x - mean) * rstd * gg.x + bb.x;
    o.y = (v.y - mean) * rstd * gg.y + bb.y;
    o.z = (v.z - mean) * rstd * gg.z + bb.z;
    o.w = (v.w - mean) * rstd * gg.w + bb.w;
    ((float4*)(y + (size_t)row * EE))[tid] = o;
}

// ---------------- GEMM: C[M,N] = epi(A[M,K] @ W[N,K]^T + bias (+ R)) ----------------
// EPI: 0 = none, 1 = elu(x)+1, 2 = relu, 3 = +residual
template <int EPI>
__global__ void __launch_bounds__(256, 2)
gemm_tn(const float* __restrict__ A, const float* __restrict__ W,
        const float* __restrict__ bias, const float* __restrict__ R,
        float* __restrict__ C, int M, int N, int K)
{
    __shared__ float As[2][16][132];
    __shared__ float Bs[2][16][132];

    const int tid = threadIdx.x;
    const int bm = blockIdx.y, bn = blockIdx.x;

    // global loaders: 64 rows per half, 4 float4 per 16-wide k slab
    const int lr = tid >> 2;             // 0..63
    const int lk = (tid & 3) * 4;        // 0,4,8,12
    const float* Ag = A + (size_t)(bm * 128 + lr) * K + lk;
    const float* Wg = W + (size_t)(bn * 128 + lr) * K + lk;
    const size_t step64 = (size_t)64 * K;

    // compute mapping: split 4+4 tiles, conflict-free
    const int warp = tid >> 5, lane = tid & 31;
    const int m0 = (warp >> 2) * 64 + (lane >> 2) * 4;   // rows m0..m0+3, m0+32..m0+35
    const int n0 = (warp & 3) * 32 + (lane & 3) * 4;     // cols n0..n0+3, n0+16..n0+19

    float acc[8][8];
    #pragma unroll
    for (int i = 0; i < 8; i++)
        #pragma unroll
        for (int j = 0; j < 8; j++) acc[i][j] = 0.f;

    const int nt = K >> 4;

    float4 ra0 = *(const float4*)(Ag);
    float4 ra1 = *(const float4*)(Ag + step64);
    float4 rb0 = *(const float4*)(Wg);
    float4 rb1 = *(const float4*)(Wg + step64);

    // store tile 0
    As[0][lk+0][lr] = ra0.x; As[0][lk+1][lr] = ra0.y; As[0][lk+2][lr] = ra0.z; As[0][lk+3][lr] = ra0.w;
    As[0][lk+0][lr+64] = ra1.x; As[0][lk+1][lr+64] = ra1.y; As[0][lk+2][lr+64] = ra1.z; As[0][lk+3][lr+64] = ra1.w;
    Bs[0][lk+0][lr] = rb0.x; Bs[0][lk+1][lr] = rb0.y; Bs[0][lk+2][lr] = rb0.z; Bs[0][lk+3][lr] = rb0.w;
    Bs[0][lk+0][lr+64] = rb1.x; Bs[0][lk+1][lr+64] = rb1.y; Bs[0][lk+2][lr+64] = rb1.z; Bs[0][lk+3][lr+64] = rb1.w;
    __syncthreads();

    for (int kt = 0; kt < nt; ++kt) {
        const int buf = kt & 1;
        if (kt + 1 < nt) {
            const float* a = Ag + (size_t)(kt + 1) * 16;
            const float* w = Wg + (size_t)(kt + 1) * 16;
            ra0 = *(const float4*)(a);
            ra1 = *(const float4*)(a + step64);
            rb0 = *(const float4*)(w);
            rb1 = *(const float4*)(w + step64);
        }
        #pragma unroll
        for (int k = 0; k < 16; ++k) {
            float4 a0 = *(const float4*)&As[buf][k][m0];
            float4 a1 = *(const float4*)&As[buf][k][m0 + 32];
            float4 b0 = *(const float4*)&Bs[buf][k][n0];
            float4 b1 = *(const float4*)&Bs[buf][k][n0 + 16];
            float av[8] = {a0.x, a0.y, a0.z, a0.w, a1.x, a1.y, a1.z, a1.w};
            float bv[8] = {b0.x, b0.y, b0.z, b0.w, b1.x, b1.y, b1.z, b1.w};
            #pragma unroll
            for (int i = 0; i < 8; i++)
                #pragma unroll
                for (int j = 0; j < 8; j++)
                    acc[i][j] += av[i] * bv[j];
        }
        if (kt + 1 < nt) {
            const int nb = (kt + 1) & 1;
            As[nb][lk+0][lr] = ra0.x; As[nb][lk+1][lr] = ra0.y; As[nb][lk+2][lr] = ra0.z; As[nb][lk+3][lr] = ra0.w;
            As[nb][lk+0][lr+64] = ra1.x; As[nb][lk+1][lr+64] = ra1.y; As[nb][lk+2][lr+64] = ra1.z; As[nb][lk+3][lr+64] = ra1.w;
            Bs[nb][lk+0][lr] = rb0.x; Bs[nb][lk+1][lr] = rb0.y; Bs[nb][lk+2][lr] = rb0.z; Bs[nb][lk+3][lr] = rb0.w;
            Bs[nb][lk+0][lr+64] = rb1.x; Bs[nb][lk+1][lr+64] = rb1.y; Bs[nb][lk+2][lr+64] = rb1.z; Bs[nb][lk+3][lr+64] = rb1.w;
        }
        __syncthreads();
    }

    // epilogue
    const float* bp = bias + bn * 128;
    float bcol[8];
    #pragma unroll
    for (int j = 0; j < 8; j++)
        bcol[j] = bp[n0 + ((j < 4) ? j : 12 + j)];   // 0..3, 16..19

    #pragma unroll
    for (int im = 0; im < 8; im++) {
        const int mr = bm * 128 + m0 + ((im < 4) ? im : 28 + im); // 0..3, 32..35
        float* crow = C + (size_t)mr * N + bn * 128;
        float v[8];
        #pragma unroll
        for (int j = 0; j < 8; j++) {
            float t = acc[im][j] + bcol[j];
            if (EPI == 1) t = (t > 0.f) ? (t + 1.f) : expf(t);     // elu + 1
            else if (EPI == 2) t = fmaxf(t, 0.f);                  // relu
            v[j] = t;
        }
        if (EPI == 3) {
            const float* rrow = R + (size_t)mr * N + bn * 128;
            float4 r0 = *(const float4*)(rrow + n0);
            float4 r1 = *(const float4*)(rrow + n0 + 16);
            v[0]+=r0.x; v[1]+=r0.y; v[2]+=r0.z; v[3]+=r0.w;
            v[4]+=r1.x; v[5]+=r1.y; v[6]+=r1.z; v[7]+=r1.w;
        }
        *(float4*)(crow + n0)      = make_float4(v[0], v[1], v[2], v[3]);
        *(float4*)(crow + n0 + 16) = make_float4(v[4], v[5], v[6], v[7]);
    }
}

// ---------------- attention stage 1: KV[bh][d][m] = sum_s K[s,d] V[s,m]; Ksum ----------------
__global__ void __launch_bounds__(256)
attn_kv_kernel(const float* __restrict__ Kf, const float* __restrict__ Vf,
               float* __restrict__ KV, float* __restrict__ Ksum)
{
    const int bh = blockIdx.x;
    const int b = bh >> 4, h = bh & 15;
    __shared__ float Ks[64][68];
    __shared__ float Vs[64][68];
    const int tid = threadIdx.x;
    const int dg = tid >> 4;            // 0..15 -> d0 = dg*4
    const int mg = tid & 15;            // 0..15 -> m0 = mg*4
    const int d0 = dg * 4, m0 = mg * 4;

    float acc[4][4];
    #pragma unroll
    for (int i = 0; i < 4; i++)
        #pragma unroll
        for (int j = 0; j < 4; j++) acc[i][j] = 0.f;
    float ksacc = 0.f;   // for tid < 64

    const size_t base0 = ((size_t)b * LL) * EE + h * DD;

    for (int s0 = 0; s0 < LL; s0 += 64) {
        // load 64x64 K and V chunks (float4)
        #pragma unroll
        for (int j = 0; j < 4; j++) {
            const int id = tid + j * 256;          // 0..1023
            const int r = id >> 4, c4 = id & 15;
            const size_t ga = base0 + (size_t)(s0 + r) * EE + c4 * 4;
            float4 kk = *(const float4*)(Kf + ga);
            float4 vv = *(const float4*)(Vf + ga);
            Ks[r][c4*4+0]=kk.x; Ks[r][c4*4+1]=kk.y; Ks[r][c4*4+2]=kk.z; Ks[r][c4*4+3]=kk.w;
            Vs[r][c4*4+0]=vv.x; Vs[r][c4*4+1]=vv.y; Vs[r][c4*4+2]=vv.z; Vs[r][c4*4+3]=vv.w;
        }
        __syncthreads();

        if (tid < 64) {
            #pragma unroll 8
            for (int s = 0; s < 64; s++) ksacc += Ks[s][tid];
        }
        #pragma unroll 4
        for (int s = 0; s < 64; s++) {
            float4 kd = *(const float4*)&Ks[s][d0];
            float4 vm = *(const float4*)&Vs[s][m0];
            float ka[4] = {kd.x, kd.y, kd.z, kd.w};
            float va[4] = {vm.x, vm.y, vm.z, vm.w};
            #pragma unroll
            for (int i = 0; i < 4; i++)
                #pragma unroll
                for (int j = 0; j < 4; j++)
                    acc[i][j] += ka[i] * va[j];
        }
        __syncthreads();
    }

    #pragma unroll
    for (int i = 0; i < 4; i++) {
        float* row = KV + ((size_t)bh * DD + (d0 + i)) * DD + m0;
        *(float4*)row = make_float4(acc[i][0], acc[i][1], acc[i][2], acc[i][3]);
    }
    if (tid < 64) Ksum[bh * DD + tid] = ksacc;
}

// ---------------- attention stage 2: out[l, h*64+m] = Z * sum_d Q[l,d] KV[d][m] ----------------
__global__ void __launch_bounds__(256)
attn_out_kernel(const float* __restrict__ Qf, const float* __restrict__ KV,
                const float* __restrict__ Ksum, float* __restrict__ Out)
{
    const int bh = blockIdx.y;
    const int b = bh >> 4, h = bh & 15;
    const int tid = threadIdx.x;
    __shared__ float KVs[64][64];
    __shared__ float ks[64];

    // load KV tile + ksum
    #pragma unroll
    for (int j = 0; j < 4; j++) {
        const int id = tid + j * 256;
        const int r = id >> 4, c4 = id & 15;
        ((float4*)&KVs[r][0])[c4] = ((const float4*)(KV + (size_t)bh * DD * DD))[id];
    }
    if (tid < 16) ((float4*)ks)[tid] = ((const float4*)(Ksum + bh * DD))[tid];
    __syncthreads();

    const int row = b * LL + blockIdx.x * 256 + tid;  // global token row
    const float4* qrow = (const float4*)(Qf + (size_t)row * EE + h * DD);

    // z = 1 / (q . ksum + eps)
    float z = 0.f;
    #pragma unroll
    for (int d4 = 0; d4 < 16; d4++) {
        float4 qv = qrow[d4];
        float4 kv = ((const float4*)ks)[d4];
        z += qv.x*kv.x + qv.y*kv.y + qv.z*kv.z + qv.w*kv.w;
    }
    const float zi = 1.0f / (z + ATTN_EPS);

    float acc[64];
    #pragma unroll
    for (int j = 0; j < 64; j++) acc[j] = 0.f;

    for (int d4 = 0; d4 < 16; d4++) {
        float4 qv = qrow[d4];
        float qs[4] = {qv.x, qv.y, qv.z, qv.w};
        #pragma unroll
        for (int dd = 0; dd < 4; dd++) {
            const float qd = qs[dd];
            const float4* kvr = (const float4*)&KVs[d4 * 4 + dd][0];
            #pragma unroll
            for (int j4 = 0; j4 < 16; j4++) {
                float4 kv = kvr[j4];
                acc[j4*4+0] += qd * kv.x;
                acc[j4*4+1] += qd * kv.y;
                acc[j4*4+2] += qd * kv.z;
                acc[j4*4+3] += qd * kv.w;
            }
        }
    }

    float* orow = Out + (size_t)row * EE + h * DD;
    #pragma unroll
    for (int j4 = 0; j4 < 16; j4++) {
        ((float4*)orow)[j4] = make_float4(acc[j4*4+0]*zi, acc[j4*4+1]*zi,
                                          acc[j4*4+2]*zi, acc[j4*4+3]*zi);
    }
}

// ---------------- host launcher ----------------
extern "C" void kernel_launch(void* const* d_in, const int* in_sizes, int n_in,
                              void* d_out, int out_size)
{
    const float* x     = (const float*)d_in[0];
    const float* ln1_g = (const float*)d_in[1];
    const float* ln1_b = (const float*)d_in[2];
    const float* ln2_g = (const float*)d_in[3];
    const float* ln2_b = (const float*)d_in[4];
    const float* Wq = (const float*)d_in[5];  const float* bq = (const float*)d_in[6];
    const float* Wk = (const float*)d_in[7];  const float* bk = (const float*)d_in[8];
    const float* Wv = (const float*)d_in[9];  const float* bv = (const float*)d_in[10];
    const float* Wo = (const float*)d_in[11]; const float* bo = (const float*)d_in[12];
    const float* W1 = (const float*)d_in[13]; const float* b1 = (const float*)d_in[14];
    const float* W2 = (const float*)d_in[15]; const float* b2 = (const float*)d_in[16];
    float* out = (float*)d_out;

    void *p_h1, *p_q, *p_k, *p_v, *p_x2, *p_f1, *p_kv, *p_ks;
    cudaGetSymbolAddress(&p_h1, g_h1);
    cudaGetSymbolAddress(&p_q,  g_q);
    cudaGetSymbolAddress(&p_k,  g_k);
    cudaGetSymbolAddress(&p_v,  g_v);
    cudaGetSymbolAddress(&p_x2, g_x2);
    cudaGetSymbolAddress(&p_f1, g_f1);
    cudaGetSymbolAddress(&p_kv, g_kv);
    cudaGetSymbolAddress(&p_ks, g_ks);
    float* h1 = (float*)p_h1;  float* q  = (float*)p_q;
    float* k  = (float*)p_k;   float* v  = (float*)p_v;
    float* x2 = (float*)p_x2;  float* f1 = (float*)p_f1;
    float* kv = (float*)p_kv;  float* ks = (float*)p_ks;

    const dim3 gE(EE / 128, MM / 128);   // N=1024 gemms
    const dim3 gF(FF / 128, MM / 128);   // N=4096 gemm

    // 1. LN1
    ln_kernel<<<MM, 256>>>(x, ln1_g, ln1_b, h1);
    // 2. QKV projections (feature map fused on Q,K)
    gemm_tn<1><<<gE, 256>>>(h1, Wq, bq, nullptr, q, MM, EE, EE);
    gemm_tn<1><<<gE, 256>>>(h1, Wk, bk, nullptr, k, MM, EE, EE);
    gemm_tn<0><<<gE, 256>>>(h1, Wv, bv, nullptr, v, MM, EE, EE);
    // 3. linear attention
    attn_kv_kernel<<<BB * HH, 256>>>(k, v, kv, ks);
    attn_out_kernel<<<dim3(LL / 256, BB * HH), 256>>>(q, kv, ks, h1); // reuse h1 as attn buf
    // 4. Wo projection + residual -> x2
    gemm_tn<3><<<gE, 256>>>(h1, Wo, bo, x, x2, MM, EE, EE);
    // 5. LN2 (reuse k as h2)
    ln_kernel<<<MM, 256>>>(x2, ln2_g, ln2_b, k);
    // 6. FFN
    gemm_tn<2><<<gF, 256>>>(k, W1, b1, nullptr, f1, MM, FF, EE);
    gemm_tn<3><<<gE, 256>>>(f1, W2, b2, x2, out, MM, EE, FF);
}

// round 3
// speedup vs baseline: 2.0366x; 2.0366x over previous
#include <cuda_runtime.h>
#include <cuda_bf16.h>
#include <math.h>
#include <stdint.h>

// Problem dims (fixed)
#define BB 8
#define LL 2048
#define EE 1024
#define HH 16
#define DD 64
#define MM (BB*LL)      // 16384 rows
#define FF (4*EE)       // 4096 ffn dim

#define LN_EPS 1e-5f
#define ATTN_EPS 1e-6f

// ======================= helpers =======================
__device__ __forceinline__ uint32_t smem_to_u32(const void* smem_ptr) {
    uint32_t addr;
    asm("{ .reg .u64 tmp; cvta.to.shared.u64 tmp, %1; cvt.u32.u64 %0, tmp; }"
        : "=r"(addr) : "l"(smem_ptr));
    return addr;
}

__device__ __forceinline__ void cp_async16(uint32_t saddr, const void* gptr) {
    asm volatile("cp.async.cg.shared.global [%0], [%1], 16;" :: "r"(saddr), "l"(gptr));
}
__device__ __forceinline__ void cp_commit() {
    asm volatile("cp.async.commit_group;");
}
template<int N>
__device__ __forceinline__ void cp_wait() {
    asm volatile("cp.async.wait_group %0;" :: "n"(N));
}

__device__ __forceinline__ void ldmatrix_x4(uint32_t* r, uint32_t addr) {
    asm volatile("ldmatrix.sync.aligned.m8n8.x4.shared.b16 {%0,%1,%2,%3}, [%4];"
                 : "=r"(r[0]), "=r"(r[1]), "=r"(r[2]), "=r"(r[3]) : "r"(addr));
}

__device__ __forceinline__ void mma16816(float* c, const uint32_t* a, uint32_t b0, uint32_t b1) {
    asm volatile(
        "mma.sync.aligned.m16n8k16.row.col.f32.bf16.bf16.f32 "
        "{%0,%1,%2,%3}, {%4,%5,%6,%7}, {%8,%9}, {%0,%1,%2,%3};"
        : "+f"(c[0]), "+f"(c[1]), "+f"(c[2]), "+f"(c[3])
        : "r"(a[0]), "r"(a[1]), "r"(a[2]), "r"(a[3]), "r"(b0), "r"(b1));
}

// ======================= scratch (device globals) =======================
__device__ __align__(256) __nv_bfloat16 g_hhi [(size_t)MM * EE];
__device__ __align__(256) __nv_bfloat16 g_hlo [(size_t)MM * EE];
__device__ __align__(256) __nv_bfloat16 g_aohi[(size_t)MM * EE];
__device__ __align__(256) __nv_bfloat16 g_aolo[(size_t)MM * EE];
__device__ __align__(256) __nv_bfloat16 g_f1hi[(size_t)MM * FF];
__device__ __align__(256) __nv_bfloat16 g_f1lo[(size_t)MM * FF];
__device__ __align__(256) float g_q [(size_t)MM * EE];
__device__ __align__(256) float g_k [(size_t)MM * EE];
__device__ __align__(256) float g_v [(size_t)MM * EE];
__device__ __align__(256) float g_x2[(size_t)MM * EE];
__device__ __align__(256) __nv_bfloat16 g_wqhi[(size_t)EE*EE], g_wqlo[(size_t)EE*EE];
__device__ __align__(256) __nv_bfloat16 g_wkhi[(size_t)EE*EE], g_wklo[(size_t)EE*EE];
__device__ __align__(256) __nv_bfloat16 g_wvhi[(size_t)EE*EE], g_wvlo[(size_t)EE*EE];
__device__ __align__(256) __nv_bfloat16 g_wohi[(size_t)EE*EE], g_wolo[(size_t)EE*EE];
__device__ __align__(256) __nv_bfloat16 g_w1hi[(size_t)FF*EE], g_w1lo[(size_t)FF*EE];
__device__ __align__(256) __nv_bfloat16 g_w2hi[(size_t)EE*FF], g_w2lo[(size_t)EE*FF];
__device__ __align__(256) float g_kv[BB * HH * DD * DD];
__device__ __align__(256) float g_ks[BB * HH * DD];

// ======================= fp32 -> bf16 hi/lo conversion =======================
__global__ void cvt_hilo_kernel(const float* __restrict__ s,
                                __nv_bfloat16* __restrict__ hi,
                                __nv_bfloat16* __restrict__ lo, int n4)
{
    int i = blockIdx.x * 256 + threadIdx.x;
    if (i >= n4) return;
    float4 v = ((const float4*)s)[i];
    __nv_bfloat16 h0 = __float2bfloat16(v.x), h1 = __float2bfloat16(v.y);
    __nv_bfloat16 h2 = __float2bfloat16(v.z), h3 = __float2bfloat16(v.w);
    ((__nv_bfloat162*)hi)[2*i]   = __halves2bfloat162(h0, h1);
    ((__nv_bfloat162*)hi)[2*i+1] = __halves2bfloat162(h2, h3);
    __nv_bfloat16 l0 = __float2bfloat16(v.x - __bfloat162float(h0));
    __nv_bfloat16 l1 = __float2bfloat16(v.y - __bfloat162float(h1));
    __nv_bfloat16 l2 = __float2bfloat16(v.z - __bfloat162float(h2));
    __nv_bfloat16 l3 = __float2bfloat16(v.w - __bfloat162float(h3));
    ((__nv_bfloat162*)lo)[2*i]   = __halves2bfloat162(l0, l1);
    ((__nv_bfloat162*)lo)[2*i+1] = __halves2bfloat162(l2, l3);
}

// ======================= LayerNorm (writes bf16 hi/lo) =======================
__global__ void ln_hilo_kernel(const float* __restrict__ x,
                               const float* __restrict__ g,
                               const float* __restrict__ b,
                               __nv_bfloat16* __restrict__ yhi,
                               __nv_bfloat16* __restrict__ ylo)
{
    const int row = blockIdx.x;
    const int tid = threadIdx.x;          // 256 threads, 4 floats each
    const float4* xr = (const float4*)(x + (size_t)row * EE);
    float4 v = xr[tid];
    float s  = v.x + v.y + v.z + v.w;
    float sq = v.x*v.x + v.y*v.y + v.z*v.z + v.w*v.w;

    #pragma unroll
    for (int off = 16; off > 0; off >>= 1) {
        s  += __shfl_xor_sync(0xffffffffu, s,  off);
        sq += __shfl_xor_sync(0xffffffffu, sq, off);
    }
    __shared__ float ws[8], wsq[8];
    __shared__ float s_mean, s_rstd;
    const int wid = tid >> 5, lane = tid & 31;
    if (lane == 0) { ws[wid] = s; wsq[wid] = sq; }
    __syncthreads();
    if (tid == 0) {
        float ts = 0.f, tsq = 0.f;
        #pragma unroll
        for (int i = 0; i < 8; i++) { ts += ws[i]; tsq += wsq[i]; }
        float mean = ts * (1.0f / EE);
        float var  = tsq * (1.0f / EE) - mean * mean;
        s_mean = mean;
        s_rstd = rsqrtf(var + LN_EPS);
    }
    __syncthreads();
    const float mean = s_mean, rstd = s_rstd;
    float4 gg = ((const float4*)g)[tid];
    float4 bb = ((const float4*)b)[tid];
    float o0 = (v.x - mean) * rstd * gg.x + bb.x;
    float o1 = (v.y - mean) * rstd * gg.y + bb.y;
    float o2 = (v.z - mean) * rstd * gg.z + bb.z;
    float o3 = (v.w - mean) * rstd * gg.w + bb.w;
    __nv_bfloat16 h0 = __float2bfloat16(o0), h1 = __float2bfloat16(o1);
    __nv_bfloat16 h2 = __float2bfloat16(o2), h3 = __float2bfloat16(o3);
    __nv_bfloat162* hp = (__nv_bfloat162*)(yhi + (size_t)row * EE + tid * 4);
    __nv_bfloat162* lp = (__nv_bfloat162*)(ylo + (size_t)row * EE + tid * 4);
    hp[0] = __halves2bfloat162(h0, h1);
    hp[1] = __halves2bfloat162(h2, h3);
    lp[0] = __halves2bfloat162(__float2bfloat16(o0 - __bfloat162float(h0)),
                               __float2bfloat16(o1 - __bfloat162float(h1)));
    lp[1] = __halves2bfloat162(__float2bfloat16(o2 - __bfloat162float(h2)),
                               __float2bfloat16(o3 - __bfloat162float(h3)));
}

// ======================= mma.sync 3xBF16 GEMM =======================
// C[M,N] = epi(A[M,K] @ W[N,K]^T + bias (+R)); A,W as bf16 hi/lo.
// CTA 128x128, 8 warps (2x4), warp tile 64x32, K-chunk 32, 3-stage cp.async ring.
// EPI: 0 none, 1 elu+1, 2 relu, 3 +residual. OUT: 0 fp32, 1 bf16 hi/lo.
#define STAGE_BYTES 32768
#define OFF_AHI 0
#define OFF_ALO 8192
#define OFF_BHI 16384
#define OFF_BLO 24576
#define GEMM_SMEM (3*STAGE_BYTES)

// swizzled smem byte offset of 16B chunk (row, c), row stride 64B, c in 0..3
__device__ __forceinline__ uint32_t swz(int row, int c) {
    return (uint32_t)(row * 64 + ((c ^ ((row >> 1) & 3)) << 4));
}

template<int EPI, int OUT>
__global__ void __launch_bounds__(256, 2)
gemm3bf(const __nv_bfloat16* __restrict__ Ahi, const __nv_bfloat16* __restrict__ Alo,
        const __nv_bfloat16* __restrict__ Bhi, const __nv_bfloat16* __restrict__ Blo,
        const float* __restrict__ bias, const float* __restrict__ Rres,
        float* __restrict__ Cf, __nv_bfloat16* __restrict__ Chi,
        __nv_bfloat16* __restrict__ Clo,
        int M, int N, int K)
{
    extern __shared__ __align__(128) char smem[];
    const uint32_t smem_u = smem_to_u32(smem);

    const int tid = threadIdx.x;
    const int wid = tid >> 5, lane = tid & 31;
    const int bm = blockIdx.y, bn = blockIdx.x;
    const int warp_m = (wid >> 2) * 64;
    const int warp_n = (wid & 3) * 32;

    const __nv_bfloat16* gAhi = Ahi + (size_t)(bm * 128) * K;
    const __nv_bfloat16* gAlo = Alo + (size_t)(bm * 128) * K;
    const __nv_bfloat16* gBhi = Bhi + (size_t)(bn * 128) * K;
    const __nv_bfloat16* gBlo = Blo + (size_t)(bn * 128) * K;

    const int nc = K >> 5;   // K-chunks of 32

    // loader: 2 iterations cover 128 rows x 4 chunks of 16B per buffer
    const int lrow0 = tid >> 2;        // 0..63
    const int lc    = tid & 3;

    auto issue_stage = [&](int c) {
        if (c < nc) {
            const uint32_t sb = smem_u + (c % 3) * STAGE_BYTES;
            const int k0 = c * 32;
            #pragma unroll
            for (int i = 0; i < 2; i++) {
                const int row = lrow0 + i * 64;
                const uint32_t so = swz(row, lc);
                const size_t go = (size_t)row * K + k0 + lc * 8;
                cp_async16(sb + OFF_AHI + so, gAhi + go);
                cp_async16(sb + OFF_ALO + so, gAlo + go);
                cp_async16(sb + OFF_BHI + so, gBhi + go);
                cp_async16(sb + OFF_BLO + so, gBlo + go);
            }
        }
        cp_commit();
    };

    float acc[4][4][4];
    #pragma unroll
    for (int i = 0; i < 4; i++)
        #pragma unroll
        for (int j = 0; j < 4; j++)
            #pragma unroll
            for (int t = 0; t < 4; t++) acc[i][j][t] = 0.f;

    issue_stage(0); issue_stage(1); issue_stage(2);

    // ldmatrix address components (per thread, per x4): row offset within 16-row tile
    const int lm_r = ((lane >> 3) & 1) * 8 + (lane & 7);   // row within tile
    const int lm_c = lane >> 4;                            // 0/1 -> chunk offset

    for (int c = 0; c < nc; c++) {
        cp_wait<2>();
        __syncthreads();
        const uint32_t sb = smem_u + (c % 3) * STAGE_BYTES;

        #pragma unroll
        for (int s = 0; s < 2; s++) {
            const int chunk = 2 * s + lm_c;
            // B fragments: 2 pairs (each covers 2 n-tiles), hi + lo
            uint32_t Bh[2][4], Bl[2][4];
            #pragma unroll
            for (int p = 0; p < 2; p++) {
                const int row = warp_n + p * 16 + lm_r;
                const uint32_t a = sb + OFF_BHI + swz(row, chunk);
                ldmatrix_x4(Bh[p], a);
                ldmatrix_x4(Bl[p], a + (OFF_BLO - OFF_BHI));
            }
            #pragma unroll
            for (int mi = 0; mi < 4; mi++) {
                const int row = warp_m + mi * 16 + lm_r;
                uint32_t Ah[4], Al[4];
                const uint32_t a = sb + OFF_AHI + swz(row, chunk);
                ldmatrix_x4(Ah, a);
                ldmatrix_x4(Al, a + (OFF_ALO - OFF_AHI));
                #pragma unroll
                for (int ni = 0; ni < 4; ni++) {
                    const int p = ni >> 1, q = ni & 1;
                    const uint32_t b0h = Bh[p][q], b1h = Bh[p][2 + q];
                    const uint32_t b0l = Bl[p][q], b1l = Bl[p][2 + q];
                    mma16816(acc[mi][ni], Ah, b0h, b1h);
                    mma16816(acc[mi][ni], Ah, b0l, b1l);
                    mma16816(acc[mi][ni], Al, b0h, b1h);
                }
            }
        }
        __syncthreads();
        issue_stage(c + 3);
    }

    // ---------------- epilogue ----------------
    const int g = lane >> 2, tig = lane & 3;
    #pragma unroll
    for (int ni = 0; ni < 4; ni++) {
        const int n = bn * 128 + warp_n + ni * 8 + tig * 2;
        const float b0 = __ldg(bias + n), b1 = __ldg(bias + n + 1);
        #pragma unroll
        for (int mi = 0; mi < 4; mi++) {
            const int m0 = bm * 128 + warp_m + mi * 16 + g;
            #pragma unroll
            for (int half = 0; half < 2; half++) {
                const int m = m0 + half * 8;
                float v0 = acc[mi][ni][half * 2 + 0] + b0;
                float v1 = acc[mi][ni][half * 2 + 1] + b1;
                if (EPI == 1) {
                    v0 = (v0 > 0.f) ? (v0 + 1.f) : expf(v0);
                    v1 = (v1 > 0.f) ? (v1 + 1.f) : expf(v1);
                } else if (EPI == 2) {
                    v0 = fmaxf(v0, 0.f); v1 = fmaxf(v1, 0.f);
                } else if (EPI == 3) {
                    const float2 rv = *(const float2*)(Rres + (size_t)m * N + n);
                    v0 += rv.x; v1 += rv.y;
                }
                if (OUT == 0) {
                    *(float2*)(Cf + (size_t)m * N + n) = make_float2(v0, v1);
                } else {
                    __nv_bfloat16 h0 = __float2bfloat16(v0);
                    __nv_bfloat16 h1 = __float2bfloat16(v1);
                    *(__nv_bfloat162*)(Chi + (size_t)m * N + n) = __halves2bfloat162(h0, h1);
                    *(__nv_bfloat162*)(Clo + (size_t)m * N + n) = __halves2bfloat162(
                        __float2bfloat16(v0 - __bfloat162float(h0)),
                        __float2bfloat16(v1 - __bfloat162float(h1)));
                }
            }
        }
    }
}

// ======================= attention stage 1 =======================
__global__ void __launch_bounds__(256)
attn_kv_kernel(const float* __restrict__ Kf, const float* __restrict__ Vf,
               float* __restrict__ KV, float* __restrict__ Ksum)
{
    const int bh = blockIdx.x;
    const int b = bh >> 4, h = bh & 15;
    __shared__ float Ks[64][68];
    __shared__ float Vs[64][68];
    const int tid = threadIdx.x;
    const int d0 = (tid >> 4) * 4, m0 = (tid & 15) * 4;

    float acc[4][4];
    #pragma unroll
    for (int i = 0; i < 4; i++)
        #pragma unroll
        for (int j = 0; j < 4; j++) acc[i][j] = 0.f;
    float ksacc = 0.f;

    const size_t base0 = ((size_t)b * LL) * EE + h * DD;

    for (int s0 = 0; s0 < LL; s0 += 64) {
        #pragma unroll
        for (int j = 0; j < 4; j++) {
            const int id = tid + j * 256;
            const int r = id >> 4, c4 = id & 15;
            const size_t ga = base0 + (size_t)(s0 + r) * EE + c4 * 4;
            float4 kk = *(const float4*)(Kf + ga);
            float4 vv = *(const float4*)(Vf + ga);
            Ks[r][c4*4+0]=kk.x; Ks[r][c4*4+1]=kk.y; Ks[r][c4*4+2]=kk.z; Ks[r][c4*4+3]=kk.w;
            Vs[r][c4*4+0]=vv.x; Vs[r][c4*4+1]=vv.y; Vs[r][c4*4+2]=vv.z; Vs[r][c4*4+3]=vv.w;
        }
        __syncthreads();

        if (tid < 64) {
            #pragma unroll 8
            for (int s = 0; s < 64; s++) ksacc += Ks[s][tid];
        }
        #pragma unroll 4
        for (int s = 0; s < 64; s++) {
            float4 kd = *(const float4*)&Ks[s][d0];
            float4 vm = *(const float4*)&Vs[s][m0];
            float ka[4] = {kd.x, kd.y, kd.z, kd.w};
            float va[4] = {vm.x, vm.y, vm.z, vm.w};
            #pragma unroll
            for (int i = 0; i < 4; i++)
                #pragma unroll
                for (int j = 0; j < 4; j++)
                    acc[i][j] += ka[i] * va[j];
        }
        __syncthreads();
    }

    #pragma unroll
    for (int i = 0; i < 4; i++) {
        float* row = KV + ((size_t)bh * DD + (d0 + i)) * DD + m0;
        *(float4*)row = make_float4(acc[i][0], acc[i][1], acc[i][2], acc[i][3]);
    }
    if (tid < 64) Ksum[bh * DD + tid] = ksacc;
}

// ======================= attention stage 2 (writes bf16 hi/lo) =======================
__global__ void __launch_bounds__(256)
attn_out_kernel(const float* __restrict__ Qf, const float* __restrict__ KV,
                const float* __restrict__ Ksum,
                __nv_bfloat16* __restrict__ Ohi, __nv_bfloat16* __restrict__ Olo)
{
    const int bh = blockIdx.y;
    const int b = bh >> 4, h = bh & 15;
    const int tid = threadIdx.x;
    __shared__ float KVs[64][64];
    __shared__ float ks[64];

    #pragma unroll
    for (int j = 0; j < 4; j++) {
        const int id = tid + j * 256;
        const int r = id >> 4, c4 = id & 15;
        ((float4*)&KVs[r][0])[c4] = ((const float4*)(KV + (size_t)bh * DD * DD))[id];
    }
    if (tid < 16) ((float4*)ks)[tid] = ((const float4*)(Ksum + bh * DD))[tid];
    __syncthreads();

    const int row = b * LL + blockIdx.x * 256 + tid;
    const float4* qrow = (const float4*)(Qf + (size_t)row * EE + h * DD);

    float z = 0.f;
    #pragma unroll
    for (int d4 = 0; d4 < 16; d4++) {
        float4 qv = qrow[d4];
        float4 kv = ((const float4*)ks)[d4];
        z += qv.x*kv.x + qv.y*kv.y + qv.z*kv.z + qv.w*kv.w;
    }
    const float zi = 1.0f / (z + ATTN_EPS);

    float acc[64];
    #pragma unroll
    for (int j = 0; j < 64; j++) acc[j] = 0.f;

    for (int d4 = 0; d4 < 16; d4++) {
        float4 qv = qrow[d4];
        float qs[4] = {qv.x, qv.y, qv.z, qv.w};
        #pragma unroll
        for (int dd = 0; dd < 4; dd++) {
            const float qd = qs[dd];
            const float4* kvr = (const float4*)&KVs[d4 * 4 + dd][0];
            #pragma unroll
            for (int j4 = 0; j4 < 16; j4++) {
                float4 kv = kvr[j4];
                acc[j4*4+0] += qd * kv.x;
                acc[j4*4+1] += qd * kv.y;
                acc[j4*4+2] += qd * kv.z;
                acc[j4*4+3] += qd * kv.w;
            }
        }
    }

    __nv_bfloat16* hp = Ohi + (size_t)row * EE + h * DD;
    __nv_bfloat16* lp = Olo + (size_t)row * EE + h * DD;
    #pragma unroll
    for (int j2 = 0; j2 < 32; j2++) {
        float a0 = acc[j2*2]   * zi;
        float a1 = acc[j2*2+1] * zi;
        __nv_bfloat16 h0 = __float2bfloat16(a0);
        __nv_bfloat16 h1 = __float2bfloat16(a1);
        ((__nv_bfloat162*)hp)[j2] = __halves2bfloat162(h0, h1);
        ((__nv_bfloat162*)lp)[j2] = __halves2bfloat162(
            __float2bfloat16(a0 - __bfloat162float(h0)),
            __float2bfloat16(a1 - __bfloat162float(h1)));
    }
}

// ======================= host launcher =======================
extern "C" void kernel_launch(void* const* d_in, const int* in_sizes, int n_in,
                              void* d_out, int out_size)
{
    const float* x     = (const float*)d_in[0];
    const float* ln1_g = (const float*)d_in[1];
    const float* ln1_b = (const float*)d_in[2];
    const float* ln2_g = (const float*)d_in[3];
    const float* ln2_b = (const float*)d_in[4];
    const float* Wq = (const float*)d_in[5];  const float* bq = (const float*)d_in[6];
    const float* Wk = (const float*)d_in[7];  const float* bk = (const float*)d_in[8];
    const float* Wv = (const float*)d_in[9];  const float* bv = (const float*)d_in[10];
    const float* Wo = (const float*)d_in[11]; const float* bo = (const float*)d_in[12];
    const float* W1 = (const float*)d_in[13]; const float* b1 = (const float*)d_in[14];
    const float* W2 = (const float*)d_in[15]; const float* b2 = (const float*)d_in[16];
    float* out = (float*)d_out;

    #define SYM(T, name, sym) T* name; { void* p; cudaGetSymbolAddress(&p, sym); name = (T*)p; }
    SYM(__nv_bfloat16, hhi, g_hhi)  SYM(__nv_bfloat16, hlo, g_hlo)
    SYM(__nv_bfloat16, aohi, g_aohi) SYM(__nv_bfloat16, aolo, g_aolo)
    SYM(__nv_bfloat16, f1hi, g_f1hi) SYM(__nv_bfloat16, f1lo, g_f1lo)
    SYM(float, q, g_q)  SYM(float, k, g_k)  SYM(float, v, g_v)  SYM(float, x2, g_x2)
    SYM(__nv_bfloat16, wqhi, g_wqhi) SYM(__nv_bfloat16, wqlo, g_wqlo)
    SYM(__nv_bfloat16, wkhi, g_wkhi) SYM(__nv_bfloat16, wklo, g_wklo)
    SYM(__nv_bfloat16, wvhi, g_wvhi) SYM(__nv_bfloat16, wvlo, g_wvlo)
    SYM(__nv_bfloat16, wohi, g_wohi) SYM(__nv_bfloat16, wolo, g_wolo)
    SYM(__nv_bfloat16, w1hi, g_w1hi) SYM(__nv_bfloat16, w1lo, g_w1lo)
    SYM(__nv_bfloat16, w2hi, g_w2hi) SYM(__nv_bfloat16, w2lo, g_w2lo)
    SYM(float, kv, g_kv) SYM(float, ks, g_ks)
    #undef SYM

    cudaFuncSetAttribute(gemm3bf<0,0>, cudaFuncAttributeMaxDynamicSharedMemorySize, GEMM_SMEM);
    cudaFuncSetAttribute(gemm3bf<1,0>, cudaFuncAttributeMaxDynamicSharedMemorySize, GEMM_SMEM);
    cudaFuncSetAttribute(gemm3bf<2,1>, cudaFuncAttributeMaxDynamicSharedMemorySize, GEMM_SMEM);
    cudaFuncSetAttribute(gemm3bf<3,0>, cudaFuncAttributeMaxDynamicSharedMemorySize, GEMM_SMEM);

    // weight conversions (fp32 -> bf16 hi/lo)
    const int nE4 = EE * EE / 4, nF4 = EE * FF / 4;
    cvt_hilo_kernel<<<(nE4 + 255) / 256, 256>>>(Wq, wqhi, wqlo, nE4);
    cvt_hilo_kernel<<<(nE4 + 255) / 256, 256>>>(Wk, wkhi, wklo, nE4);
    cvt_hilo_kernel<<<(nE4 + 255) / 256, 256>>>(Wv, wvhi, wvlo, nE4);
    cvt_hilo_kernel<<<(nE4 + 255) / 256, 256>>>(Wo, wohi, wolo, nE4);
    cvt_hilo_kernel<<<(nF4 + 255) / 256, 256>>>(W1, w1hi, w1lo, nF4);
    cvt_hilo_kernel<<<(nF4 + 255) / 256, 256>>>(W2, w2hi, w2lo, nF4);

    const dim3 gE(EE / 128, MM / 128);   // (8, 128)
    const dim3 gF(FF / 128, MM / 128);   // (32, 128)

    // 1. LN1 -> h hi/lo
    ln_hilo_kernel<<<MM, 256>>>(x, ln1_g, ln1_b, hhi, hlo);
    // 2. QKV projections (elu+1 fused on Q,K)
    gemm3bf<1,0><<<gE, 256, GEMM_SMEM>>>(hhi, hlo, wqhi, wqlo, bq, nullptr, q, nullptr, nullptr, MM, EE, EE);
    gemm3bf<1,0><<<gE, 256, GEMM_SMEM>>>(hhi, hlo, wkhi, wklo, bk, nullptr, k, nullptr, nullptr, MM, EE, EE);
    gemm3bf<0,0><<<gE, 256, GEMM_SMEM>>>(hhi, hlo, wvhi, wvlo, bv, nullptr, v, nullptr, nullptr, MM, EE, EE);
    // 3. linear attention
    attn_kv_kernel<<<BB * HH, 256>>>(k, v, kv, ks);
    attn_out_kernel<<<dim3(LL / 256, BB * HH), 256>>>(q, kv, ks, aohi, aolo);
    // 4. Wo projection + residual -> x2
    gemm3bf<3,0><<<gE, 256, GEMM_SMEM>>>(aohi, aolo, wohi, wolo, bo, x, x2, nullptr, nullptr, MM, EE, EE);
    // 5. LN2 -> h hi/lo (reuse)
    ln_hilo_kernel<<<MM, 256>>>(x2, ln2_g, ln2_b, hhi, hlo);
    // 6. FFN
    gemm3bf<2,1><<<gF, 256, GEMM_SMEM>>>(hhi, hlo, w1hi, w1lo, b1, nullptr, nullptr, f1hi, f1lo, MM, FF, EE);
    gemm3bf<3,0><<<gE, 256, GEMM_SMEM>>>(f1hi, f1lo, w2hi, w2lo, b2, x2, out, nullptr, nullptr, MM, EE, FF);
}